// round 3
// baseline (speedup 1.0000x reference)
#include <cuda_runtime.h>

#define S_LEN 4096
#define D_DIM 300
#define H_DIM 300
#define HU    150
#define G4    600   // 4*HU

// ---------------- scratch (static device globals; no allocation) ----------------
__device__ float g_xW[2][S_LEN * G4];        // x@W + b, per direction (bwd pre-reversed)
__device__ float g_hidden[S_LEN * H_DIM];    // [S,300]: cols 0..149 fwd, 150..299 bwd
__device__ float g_attout[S_LEN * H_DIM];    // hidden @ W_p + b_p
__device__ float g_m[S_LEN * D_DIM];         // attention m vectors
__device__ float g_coeff[S_LEN];             // secondary attention coeffs
__device__ float g_partial[64 * G4];         // deterministic reduction partials

// ---------------- helpers ----------------
__device__ __forceinline__ unsigned long long ffma2(unsigned long long a,
                                                    unsigned long long b,
                                                    unsigned long long c) {
    unsigned long long d;
    asm("fma.rn.f32x2 %0, %1, %2, %3;" : "=l"(d) : "l"(a), "l"(b), "l"(c));
    return d;
}
__device__ __forceinline__ unsigned long long pack2(float lo, float hi) {
    unsigned long long p;
    asm("mov.b64 %0, {%1, %2};" : "=l"(p) : "f"(lo), "f"(hi));
    return p;
}
__device__ __forceinline__ void unpack2(unsigned long long v, float& lo, float& hi) {
    asm("mov.b64 {%0, %1}, %2;" : "=f"(lo), "=f"(hi) : "l"(v));
}
__device__ __forceinline__ void cluster_sync_() {
    asm volatile("barrier.cluster.arrive.aligned;" ::: "memory");
    asm volatile("barrier.cluster.wait.aligned;" ::: "memory");
}
__device__ __forceinline__ float sigmoidf_(float x) {
    return 0.5f * tanhf(0.5f * x) + 0.5f;
}

// ---------------- K1: xW = gather(emb) @ W_dir + b_dir (bwd rows pre-reversed) ----------------
__global__ __launch_bounds__(608, 2)
void xw_kernel(const int* __restrict__ sent, const float* __restrict__ E,
               const float* __restrict__ W_f, const float* __restrict__ b_f,
               const float* __restrict__ W_b, const float* __restrict__ b_b) {
    const int dir = blockIdx.y;
    const int s0  = blockIdx.x * 16;
    const float* __restrict__ W  = dir ? W_b : W_f;
    const float* __restrict__ bv = dir ? b_b : b_f;
    __shared__ float esm[16 * D_DIM];
    const int tid = threadIdx.x;
    for (int i = tid; i < 16 * D_DIM; i += 608) {
        int r = i / D_DIM, k = i - r * D_DIM;
        int srow = dir ? (S_LEN - 1 - (s0 + r)) : (s0 + r);
        esm[i] = E[(long long)sent[srow] * D_DIM + k];
    }
    __syncthreads();
    const int j = tid;
    if (j < G4) {
        float acc[16];
#pragma unroll
        for (int r = 0; r < 16; r++) acc[r] = 0.f;
        for (int k = 0; k < D_DIM; k++) {
            float w = W[k * G4 + j];
#pragma unroll
            for (int r = 0; r < 16; r++) acc[r] = fmaf(esm[r * D_DIM + k], w, acc[r]);
        }
        float bb = bv[j];
#pragma unroll
        for (int r = 0; r < 16; r++) g_xW[dir][(s0 + r) * G4 + j] = acc[r] + bb;
    }
}

// ---------------- K2: persistent biLSTM. 2 clusters of 2 CTAs (one cluster/dir). ----------------
// CTA rank owns cells m in [rank*75, rank*75+75); all 4 gate columns for those cells.
// U columns register-resident (150 floats/thread, packed f32x2 over K).
__global__ void __cluster_dims__(2, 1, 1) __launch_bounds__(320, 1)
lstm_kernel(const float* __restrict__ U_f, const float* __restrict__ U_b) {
    const int dir = blockIdx.x >> 1;
    unsigned int rank;
    asm("mov.u32 %0, %%cluster_ctarank;" : "=r"(rank));
    const int tid = threadIdx.x;
    const float* __restrict__ U  = dir ? U_b : U_f;
    const float* __restrict__ xW = g_xW[dir];

    __shared__ float2 h2sm[2][80];   // double-buffered h (150 used of 160)
    __shared__ float  act_sm[304];

    // zero both h buffers (320 floats exactly)
    ((float*)h2sm)[tid] = 0.f;
    __syncthreads();

    const int gate  = tid / 75;           // 0=i 1=f 2=g 3=o (for tid<300)
    const int m_loc = tid - gate * 75;
    const int m     = (int)rank * 75 + m_loc;
    const int j     = gate * HU + m;      // column in [0,600)

    unsigned long long u64[75];
    if (tid < 300) {
#pragma unroll
        for (int kk = 0; kk < 75; kk++)
            u64[kk] = pack2(U[(2 * kk) * G4 + j], U[(2 * kk + 1) * G4 + j]);
    }
    float c = 0.f;

    // remote (peer CTA) base addresses of the two h buffers
    unsigned int lbase0 = (unsigned int)__cvta_generic_to_shared(&h2sm[0][0]);
    unsigned int lbase1 = (unsigned int)__cvta_generic_to_shared(&h2sm[1][0]);
    unsigned int peer = rank ^ 1u;
    unsigned int rbase0, rbase1;
    asm("mapa.shared::cluster.u32 %0, %1, %2;" : "=r"(rbase0) : "r"(lbase0), "r"(peer));
    asm("mapa.shared::cluster.u32 %0, %1, %2;" : "=r"(rbase1) : "r"(lbase1), "r"(peer));

    cluster_sync_();

    for (int t = 0; t < S_LEN; t++) {
        const int rb = t & 1;
        if (tid < 300) {
            float xwv = xW[t * G4 + j];
            const unsigned long long* hp = (const unsigned long long*)&h2sm[rb][0];
            unsigned long long a0 = 0ull, a1 = 0ull, a2 = 0ull;  // (0.f,0.f)
#pragma unroll
            for (int kk = 0; kk < 75; kk += 3) {
                a0 = ffma2(u64[kk],     hp[kk],     a0);
                a1 = ffma2(u64[kk + 1], hp[kk + 1], a1);
                a2 = ffma2(u64[kk + 2], hp[kk + 2], a2);
            }
            float x0, x1, y0, y1, z0, z1;
            unpack2(a0, x0, x1); unpack2(a1, y0, y1); unpack2(a2, z0, z1);
            float z = xwv + ((x0 + x1) + (y0 + y1) + (z0 + z1));
            act_sm[tid] = (gate == 2) ? tanhf(z) : sigmoidf_(z);
        }
        __syncthreads();
        if (tid < 75) {
            float iv = act_sm[tid];
            float fv = act_sm[75 + tid];
            float gv = act_sm[150 + tid];
            float ov = act_sm[225 + tid];
            c = fmaf(fv, c, iv * gv);
            float hv = ov * tanhf(c);
            const int wb = rb ^ 1;
            ((float*)&h2sm[wb][0])[m] = hv;
            unsigned int raddr = (wb ? rbase1 : rbase0) + (unsigned)m * 4u;
            asm volatile("st.shared::cluster.f32 [%0], %1;" :: "r"(raddr), "f"(hv) : "memory");
            const int row = dir ? (S_LEN - 1 - t) : t;
            g_hidden[row * H_DIM + dir * HU + m] = hv;
        }
        cluster_sync_();   // release own/remote h stores; acquire peer's
    }
}

// ---------------- K3: attout = hidden @ W_p + b_p ----------------
__global__ __launch_bounds__(320, 2)
void attdense_kernel(const float* __restrict__ W_p, const float* __restrict__ b_p) {
    const int s0 = blockIdx.x * 16;
    __shared__ float hsm[16 * H_DIM];
    const int tid = threadIdx.x;
    for (int i = tid; i < 16 * H_DIM; i += 320) hsm[i] = g_hidden[s0 * H_DIM + i];
    __syncthreads();
    const int j = tid;
    if (j < H_DIM) {
        float acc[16];
#pragma unroll
        for (int r = 0; r < 16; r++) acc[r] = 0.f;
        for (int k = 0; k < H_DIM; k++) {
            float w = W_p[k * H_DIM + j];
#pragma unroll
            for (int r = 0; r < 16; r++) acc[r] = fmaf(hsm[r * H_DIM + k], w, acc[r]);
        }
        float bb = b_p[j];
#pragma unroll
        for (int r = 0; r < 16; r++) g_attout[(s0 + r) * H_DIM + j] = acc[r] + bb;
    }
}

// ---------------- K4: per-word synonym attention + secondary coeff ----------------
__device__ __forceinline__ float block_reduce_320(float v, float* red, int lane, int wid) {
#pragma unroll
    for (int off = 16; off; off >>= 1) v += __shfl_down_sync(0xffffffffu, v, off);
    __syncthreads();               // protect red from previous reduction's readers
    if (lane == 0) red[wid] = v;
    __syncthreads();
    float t = 0.f;
#pragma unroll
    for (int w = 0; w < 10; w++) t += red[w];
    return t;                      // every thread returns the same value
}

__global__ __launch_bounds__(320)
void attn_kernel(const int* __restrict__ syn_idx, const float* __restrict__ E,
                 const float* __restrict__ W_s, const float* __restrict__ b_s) {
    const int s   = blockIdx.x;
    const int tid = threadIdx.x;
    const int lane = tid & 31, wid = tid >> 5;
    __shared__ float red[10];
    const bool active = tid < D_DIM;

    float od = 0.f, hd = 0.f;
    float ev[4] = {0.f, 0.f, 0.f, 0.f};
    if (active) {
        od = g_attout[s * H_DIM + tid];
        hd = g_hidden[s * H_DIM + tid];
#pragma unroll
        for (int k = 0; k < 4; k++)
            ev[k] = E[(long long)syn_idx[s * 4 + k] * D_DIM + tid];
    }
    float sc[4];
#pragma unroll
    for (int k = 0; k < 4; k++) {
        float dot = block_reduce_320(od * ev[k], red, lane, wid);
        sc[k] = expf(dot);
    }
    float md = sc[0] * ev[0] + sc[1] * ev[1] + sc[2] * ev[2] + sc[3] * ev[3];
    if (active) g_m[s * D_DIM + tid] = md;
    float cv = active ? (hd * W_s[tid] + md * W_s[D_DIM + tid]) : 0.f;
    float tot = block_reduce_320(cv, red, lane, wid);
    if (tid == 0) g_coeff[s] = expf(tanhf(tot + b_s[0]));
}

// ---------------- K5: deterministic partial reduction of coeff * h_hat ----------------
__global__ __launch_bounds__(608)
void reduce1_kernel() {
    const int b = blockIdx.x;
    const int j = threadIdx.x;
    if (j >= G4) return;
    float acc = 0.f;
    const int s0 = b * 64;
    for (int s = s0; s < s0 + 64; s++) {
        float cf = g_coeff[s];
        float v  = (j < H_DIM) ? g_hidden[s * H_DIM + j] : g_m[s * D_DIM + (j - H_DIM)];
        acc = fmaf(cf, v, acc);
    }
    g_partial[b * G4 + j] = acc;
}

// ---------------- K6: final sum + output heads ----------------
__global__ __launch_bounds__(608)
void final_kernel(const float* __restrict__ W_emo, const float* __restrict__ b_emo,
                  const float* __restrict__ W_sent, const float* __restrict__ b_sent,
                  float* __restrict__ out) {
    __shared__ float HH[G4];
    const int j = threadIdx.x;
    if (j < G4) {
        float a = 0.f;
        for (int b = 0; b < 64; b++) a += g_partial[b * G4 + j];
        HH[j] = a;
    }
    __syncthreads();
    if (j < 8) {
        float a = b_emo[j];
        for (int k = 0; k < G4; k++) a = fmaf(HH[k], W_emo[k * 8 + j], a);
        out[j] = a;
    } else if (j == 8) {
        float a = b_sent[0];
        for (int k = 0; k < G4; k++) a = fmaf(HH[k], W_sent[k], a);
        out[8] = a;
    }
}

// ---------------- launch ----------------
extern "C" void kernel_launch(void* const* d_in, const int* in_sizes, int n_in,
                              void* d_out, int out_size) {
    const int*   sent   = (const int*)d_in[0];
    const int*   syn    = (const int*)d_in[1];
    const float* E      = (const float*)d_in[2];
    const float* W_f    = (const float*)d_in[3];
    const float* U_f    = (const float*)d_in[4];
    const float* b_f    = (const float*)d_in[5];
    const float* W_b    = (const float*)d_in[6];
    const float* U_b    = (const float*)d_in[7];
    const float* b_b    = (const float*)d_in[8];
    const float* W_p    = (const float*)d_in[9];
    const float* b_p    = (const float*)d_in[10];
    const float* W_s    = (const float*)d_in[11];
    const float* b_s    = (const float*)d_in[12];
    const float* W_emo  = (const float*)d_in[13];
    const float* b_emo  = (const float*)d_in[14];
    const float* W_sent = (const float*)d_in[15];
    const float* b_sent = (const float*)d_in[16];
    float* out = (float*)d_out;

    dim3 gxw(S_LEN / 16, 2);
    xw_kernel<<<gxw, 608>>>(sent, E, W_f, b_f, W_b, b_b);
    lstm_kernel<<<4, 320>>>(U_f, U_b);                 // 2 clusters x 2 CTAs
    attdense_kernel<<<S_LEN / 16, 320>>>(W_p, b_p);
    attn_kernel<<<S_LEN, 320>>>(syn, E, W_s, b_s);
    reduce1_kernel<<<64, 608>>>();
    final_kernel<<<1, 608>>>(W_emo, b_emo, W_sent, b_sent, out);
}